// round 14
// baseline (speedup 1.0000x reference)
#include <cuda_runtime.h>
#include <cstdint>

#define NTOK 8192
#define KT   64
#define CHUNKS (NTOK / KT)   // 128

// passB smem layout (float indices) — R8 map
#define GOFF   0                 // g_s[128][8]
#define UOFF   1024              // u_s[2][64*72]
#define UBUF   4608
#define EOFF   10240             // e_s[2][128*68]
#define EBUF   8704
#define STOFF  1024              // st_s[128][74] epilogue alias
#define SMEM_FLOATS 27648        // 110592 bytes

// Scratch (allocation-free rule: __device__ globals)
__device__ float d_F [2 * NTOK * 8];
__device__ float d_GT[2 * NTOK * 8];
__device__ float d_VT[2 * NTOK * 64];
__device__ float d_invden[2 * NTOK];

__device__ __forceinline__ uint32_t to_tf32(float x) {
    uint32_t r; asm("cvt.rna.tf32.f32 %0, %1;" : "=r"(r) : "f"(x)); return r;
}
__device__ __forceinline__ void mma_tf32(float* d, uint32_t a0, uint32_t a1,
                                         uint32_t a2, uint32_t a3,
                                         uint32_t b0, uint32_t b1) {
    asm volatile(
        "mma.sync.aligned.m16n8k8.row.col.f32.tf32.tf32.f32 "
        "{%0,%1,%2,%3}, {%4,%5,%6,%7}, {%8,%9}, {%0,%1,%2,%3};"
        : "+f"(d[0]), "+f"(d[1]), "+f"(d[2]), "+f"(d[3])
        : "r"(a0), "r"(a1), "r"(a2), "r"(a3), "r"(b0), "r"(b1));
}
__device__ __forceinline__ void ldsm_x4(uint32_t& r0, uint32_t& r1,
                                        uint32_t& r2, uint32_t& r3, uint32_t addr) {
    asm volatile("ldmatrix.sync.aligned.m8n8.x4.shared.b16 {%0,%1,%2,%3}, [%4];"
                 : "=r"(r0), "=r"(r1), "=r"(r2), "=r"(r3) : "r"(addr));
}
__device__ __forceinline__ uint32_t smem_u32(const void* p) {
    uint32_t a;
    asm("{ .reg .u64 t; cvta.to.shared.u64 t, %1; cvt.u32.u64 %0, t; }" : "=r"(a) : "l"(p));
    return a;
}

// ---------------------------------------------------------------------------
// Kernel 1 (proven, 26us): projections.  grid (128,2) x 256.
// ---------------------------------------------------------------------------
__global__ __launch_bounds__(256) void proj_kernel(
    const float* __restrict__ x1, const float* __restrict__ x2,
    const float* __restrict__ Wf, const float* __restrict__ bf,
    const float* __restrict__ Wg, const float* __restrict__ bg,
    const float* __restrict__ Wh1, const float* __restrict__ bh1,
    const float* __restrict__ Wh2, const float* __restrict__ bh2)
{
    const int input = blockIdx.y;
    const float* __restrict__ x  = input ? x2  : x1;
    const float* __restrict__ Wh = input ? Wh2 : Wh1;
    const float* __restrict__ bh = input ? bh2 : bh1;

    __shared__ float x_s[64][65];
    __shared__ float Wh_s[64 * 64];
    __shared__ float Wfg_s[16 * 64];
    __shared__ float bh_s[64], bfg_s[16];

    const int tid = threadIdx.x;
    for (int i = tid; i < 64 * 64; i += 256) Wh_s[i] = Wh[i];
    for (int i = tid; i < 16 * 64; i += 256) Wfg_s[i] = (i < 512) ? Wf[i] : Wg[i - 512];
    if (tid < 64) bh_s[tid] = bh[tid];
    if (tid < 16) bfg_s[tid] = (tid < 8) ? bf[tid] : bg[tid - 8];

    const int n0 = blockIdx.x * 64;
    for (int i = tid; i < 64 * 64; i += 256) {
        const int c = i >> 6, t = i & 63;
        x_s[c][t] = x[(size_t)c * NTOK + n0 + t];
    }
    __syncthreads();

    const int tok = tid & 63, og = tid >> 6;
    const int n = n0 + tok;

    float xr[64];
    #pragma unroll
    for (int c = 0; c < 64; c++) xr[c] = x_s[c][tok];

    float* VT = d_VT + (size_t)(input * NTOK + n) * 64 + og * 16;
    #pragma unroll
    for (int grp = 0; grp < 4; grp++) {
        float vo[4];
        #pragma unroll
        for (int u = 0; u < 4; u++) {
            const int o = og * 16 + grp * 4 + u;
            float a = bh_s[o];
            const float4* w4 = (const float4*)&Wh_s[o * 64];
            #pragma unroll
            for (int q = 0; q < 16; q++) {
                float4 w = w4[q];
                a = fmaf(w.x, xr[4*q+0], a); a = fmaf(w.y, xr[4*q+1], a);
                a = fmaf(w.z, xr[4*q+2], a); a = fmaf(w.w, xr[4*q+3], a);
            }
            vo[u] = a;
        }
        *(float4*)&VT[grp * 4] = make_float4(vo[0], vo[1], vo[2], vo[3]);
    }

    if (og < 2) {
        float fo[8];
        #pragma unroll
        for (int o8 = 0; o8 < 8; o8++) {
            const int o = og * 8 + o8;
            float a = bfg_s[o];
            const float4* w4 = (const float4*)&Wfg_s[o * 64];
            #pragma unroll
            for (int q = 0; q < 16; q++) {
                float4 w = w4[q];
                a = fmaf(w.x, xr[4*q+0], a); a = fmaf(w.y, xr[4*q+1], a);
                a = fmaf(w.z, xr[4*q+2], a); a = fmaf(w.w, xr[4*q+3], a);
            }
            fo[o8] = a;
        }
        float4* dst = (og == 0) ? (float4*)&d_F [(size_t)(input * NTOK + n) * 8]
                                : (float4*)&d_GT[(size_t)(input * NTOK + n) * 8];
        dst[0] = make_float4(fo[0], fo[1], fo[2], fo[3]);
        dst[1] = make_float4(fo[4], fo[5], fo[6], fo[7]);
    }
}

// ---------------------------------------------------------------------------
// Kernel 2: invden via tf32 MMA logits, 512 threads (2-way m-split/row).
// grid (64,2) x 512.  wid&7 -> 16-row group; wid>>3 -> m-half (4096 each).
// Partials combined through smem.
// ---------------------------------------------------------------------------
__global__ __launch_bounds__(512) void passA_kernel()
{
    const int input = blockIdx.y;
    const int tid = threadIdx.x;
    const int wid = tid >> 5, lane = tid & 31;
    const int g4 = lane >> 2, q4 = lane & 3;
    const int w8 = wid & 7, mhalf = wid >> 3;
    const int nr = blockIdx.x * 128 + w8 * 16;

    __shared__ float part[2][128];

    const float* F = d_F + (size_t)(input * NTOK + nr) * 8;
    const uint32_t a0 = to_tf32(F[ g4      * 8 + q4]);
    const uint32_t a1 = to_tf32(F[(g4 + 8) * 8 + q4]);
    const uint32_t a2 = to_tf32(F[ g4      * 8 + q4 + 4]);
    const uint32_t a3 = to_tf32(F[(g4 + 8) * 8 + q4 + 4]);

    const float* G = d_GT + (size_t)input * NTOK * 8;
    float sum0 = 0.f, sum1 = 0.f;

    const int m_begin = mhalf * (NTOK / 2);
    const int m_end   = m_begin + (NTOK / 2);
    for (int m0 = m_begin; m0 < m_end; m0 += 64) {
        #pragma unroll
        for (int t = 0; t < 8; t++) {
            const float* gp = G + (size_t)(m0 + t * 8 + g4) * 8;
            const uint32_t b0 = to_tf32(__ldg(gp + q4));
            const uint32_t b1 = to_tf32(__ldg(gp + q4 + 4));
            float d[4] = {0.f, 0.f, 0.f, 0.f};
            mma_tf32(d, a0, a1, a2, a3, b0, b1);
            sum0 += __expf(d[0]) + __expf(d[1]);
            sum1 += __expf(d[2]) + __expf(d[3]);
        }
    }
    sum0 += __shfl_xor_sync(0xffffffffu, sum0, 1);
    sum0 += __shfl_xor_sync(0xffffffffu, sum0, 2);
    sum1 += __shfl_xor_sync(0xffffffffu, sum1, 1);
    sum1 += __shfl_xor_sync(0xffffffffu, sum1, 2);
    if (q4 == 0) {
        part[mhalf][w8 * 16 + g4]     = sum0;
        part[mhalf][w8 * 16 + g4 + 8] = sum1;
    }
    __syncthreads();
    if (tid < 128) {
        d_invden[input * NTOK + blockIdx.x * 128 + tid] =
            1.0f / (part[0][tid] + part[1][tid]);
    }
}

// ---------------------------------------------------------------------------
// Kernel 3 (R13, proven 303us): passB.  Warp tiles 32m x 32c, 2-way k-split.
// grid (64,2) x 512.
// ---------------------------------------------------------------------------
__global__ __launch_bounds__(512, 1) void passB_kernel(
    const float* __restrict__ x1, const float* __restrict__ x2,
    const float* __restrict__ g1, const float* __restrict__ g2,
    float* __restrict__ out)
{
    extern __shared__ float smf[];
    float*    g_s  = smf + GOFF;
    uint32_t* u_s  = (uint32_t*)(smf + UOFF);
    uint32_t* e_s  = (uint32_t*)(smf + EOFF);
    float*    st_s = smf + STOFF;

    const int tid = threadIdx.x;
    const int wid = tid >> 5, lane = tid & 31;
    const int g4 = lane >> 2, q4 = lane & 3;
    const int input = blockIdx.y;
    const int m_base = blockIdx.x * 128;

    {
        const float* src = d_GT + (size_t)input * NTOK * 8 + (size_t)m_base * 8;
        for (int i = tid; i < 128 * 8; i += 512) g_s[i] = src[i];
    }

    const int n_e = tid & 63, mgrp = tid >> 6;
    const float* VT  = d_VT + (size_t)input * NTOK * 64;
    const float* INV = d_invden + input * NTOK;
    const float4* Fb = (const float4*)(d_F + (size_t)input * NTOK * 8);

    const int mrow  = (wid & 3) * 32;
    const int chalf = (wid >> 2) & 1;
    const int khalf = wid >> 3;
    const int cb    = chalf * 4;

    const uint32_t e_smaddr = smem_u32(e_s);
    const uint32_t a_row = (uint32_t)(mrow + (lane & 7) + (((lane >> 3) & 1) << 3));
    const uint32_t a_base_off = (a_row * 68u + (((lane >> 4) & 1) << 2)) * 4u;

    float acc[2][4][4];
    #pragma unroll
    for (int mt = 0; mt < 2; mt++)
        #pragma unroll
        for (int t = 0; t < 4; t++)
            #pragma unroll
            for (int r = 0; r < 4; r++) acc[mt][t][r] = 0.f;

    float4 fA, fB, vv[2]; float iv[2];

#define LOADG(ch_)                                                             \
    {                                                                          \
        const int nn = (ch_) * KT;                                             \
        fA = Fb[(size_t)(nn + n_e) * 2]; fB = Fb[(size_t)(nn + n_e) * 2 + 1];  \
        _Pragma("unroll")                                                      \
        for (int k = 0; k < 2; k++) {                                          \
            const int idx = tid + 512 * k;                                     \
            const int n = idx >> 4, c4 = idx & 15;                             \
            vv[k] = ((const float4*)VT)[(size_t)(nn + n) * 16 + c4];           \
            iv[k] = INV[nn + n];                                               \
        }                                                                      \
    }

#define GENSTORE(bufi)                                                         \
    {                                                                          \
        uint32_t* ub = u_s + (bufi) * UBUF;                                    \
        uint32_t* eb = e_s + (bufi) * EBUF;                                    \
        _Pragma("unroll")                                                      \
        for (int k = 0; k < 2; k++) {                                          \
            const int idx = tid + 512 * k;                                     \
            const int n = idx >> 4, c4 = idx & 15;                             \
            uint4 p;                                                           \
            p.x = to_tf32(vv[k].x * iv[k]); p.y = to_tf32(vv[k].y * iv[k]);    \
            p.z = to_tf32(vv[k].z * iv[k]); p.w = to_tf32(vv[k].w * iv[k]);    \
            *(uint4*)&ub[n * 72 + c4 * 4] = p;                                 \
        }                                                                      \
        _Pragma("unroll")                                                      \
        for (int j = 0; j < 16; j++) {                                         \
            const int m = mgrp * 16 + j;                                       \
            const float4 ga = *(const float4*)&g_s[m * 8];                     \
            const float4 gb = *(const float4*)&g_s[m * 8 + 4];                 \
            float s = fA.x * ga.x;                                             \
            s = fmaf(fA.y, ga.y, s); s = fmaf(fA.z, ga.z, s);                  \
            s = fmaf(fA.w, ga.w, s);                                           \
            s = fmaf(fB.x, gb.x, s); s = fmaf(fB.y, gb.y, s);                  \
            s = fmaf(fB.z, gb.z, s); s = fmaf(fB.w, gb.w, s);                  \
            eb[m * 68 + n_e] = to_tf32(__expf(s));                             \
        }                                                                      \
    }

    LOADG(0);
    GENSTORE(0);
    LOADG(1);
    __syncthreads();

    for (int chunk = 0; chunk < CHUNKS; chunk++) {
        const int buf = chunk & 1;

        if (chunk + 1 < CHUNKS) {
            GENSTORE(buf ^ 1);
            if (chunk + 2 < CHUNKS) LOADG(chunk + 2);
        }

        {
            const uint32_t* ub = u_s + buf * UBUF;
            const uint32_t abase = e_smaddr + (uint32_t)(buf * EBUF * 4) + a_base_off;
            #pragma unroll
            for (int kl = 0; kl < 4; kl++) {
                const int kk = khalf * 4 + kl;
                uint32_t a0, a1, a2, a3, c0r, c1r, c2r, c3r;
                ldsm_x4(a0, a1, a2, a3, abase + (uint32_t)kk * 32u);
                ldsm_x4(c0r, c1r, c2r, c3r, abase + 4352u + (uint32_t)kk * 32u);
                #pragma unroll
                for (int ct = 0; ct < 4; ct++) {
                    const uint32_t b0 = ub[(kk * 8 + q4)     * 72 + (cb + ct) * 8 + g4];
                    const uint32_t b1 = ub[(kk * 8 + q4 + 4) * 72 + (cb + ct) * 8 + g4];
                    mma_tf32(acc[0][ct], a0, a1, a2, a3, b0, b1);
                    mma_tf32(acc[1][ct], c0r, c1r, c2r, c3r, b0, b1);
                }
            }
        }
        __syncthreads();
    }
#undef LOADG
#undef GENSTORE

    // ---- k-reduction through st_s, then epilogue ----
    if (khalf == 1) {
        #pragma unroll
        for (int mt = 0; mt < 2; mt++)
            #pragma unroll
            for (int ct = 0; ct < 4; ct++) {
                const int c = (cb + ct) * 8 + q4 * 2;
                const int r0 = mrow + mt * 16 + g4;
                *(float2*)&st_s[ r0      * 74 + c] = make_float2(acc[mt][ct][0], acc[mt][ct][1]);
                *(float2*)&st_s[(r0 + 8) * 74 + c] = make_float2(acc[mt][ct][2], acc[mt][ct][3]);
            }
    }
    __syncthreads();
    if (khalf == 0) {
        #pragma unroll
        for (int mt = 0; mt < 2; mt++)
            #pragma unroll
            for (int ct = 0; ct < 4; ct++) {
                const int c = (cb + ct) * 8 + q4 * 2;
                const int r0 = mrow + mt * 16 + g4;
                float2 p0 = *(float2*)&st_s[ r0      * 74 + c];
                float2 p1 = *(float2*)&st_s[(r0 + 8) * 74 + c];
                p0.x += acc[mt][ct][0]; p0.y += acc[mt][ct][1];
                p1.x += acc[mt][ct][2]; p1.y += acc[mt][ct][3];
                *(float2*)&st_s[ r0      * 74 + c] = p0;
                *(float2*)&st_s[(r0 + 8) * 74 + c] = p1;
            }
    }
    __syncthreads();
    {
        const float* __restrict__ x = input ? x2 : x1;
        const float gamma = input ? __ldg(g2) : __ldg(g1);
        #pragma unroll
        for (int j = 0; j < 4; j++) {
            const int c = wid * 4 + j;
            const size_t rowx = (size_t)c * NTOK + m_base;
            const size_t rowo = (size_t)(input * 64 + c) * NTOK + m_base;
            #pragma unroll
            for (int jj = 0; jj < 4; jj++) {
                const int m = lane + 32 * jj;
                out[rowo + m] = fmaf(gamma, st_s[m * 74 + c], x[rowx + m]);
            }
        }
    }
}

// ---------------------------------------------------------------------------
extern "C" void kernel_launch(void* const* d_in, const int* in_sizes, int n_in,
                              void* d_out, int out_size)
{
    (void)in_sizes; (void)n_in; (void)out_size;
    const float* x1  = (const float*)d_in[0];
    const float* x2  = (const float*)d_in[1];
    const float* Wf  = (const float*)d_in[2];
    const float* bf  = (const float*)d_in[3];
    const float* Wg  = (const float*)d_in[4];
    const float* bg  = (const float*)d_in[5];
    const float* Wh1 = (const float*)d_in[6];
    const float* bh1 = (const float*)d_in[7];
    const float* Wh2 = (const float*)d_in[8];
    const float* bh2 = (const float*)d_in[9];
    const float* g1  = (const float*)d_in[10];
    const float* g2  = (const float*)d_in[11];
    float* out = (float*)d_out;

    cudaFuncSetAttribute(passB_kernel, cudaFuncAttributeMaxDynamicSharedMemorySize,
                         SMEM_FLOATS * 4);

    dim3 gp(NTOK / 64, 2);
    proj_kernel<<<gp, 256>>>(x1, x2, Wf, bf, Wg, bg, Wh1, bh1, Wh2, bh2);
    dim3 ga(NTOK / 128, 2);
    passA_kernel<<<ga, 512>>>();
    dim3 gb(NTOK / 128, 2);
    passB_kernel<<<gb, 512, SMEM_FLOATS * 4>>>(x1, x2, g1, g2, out);
}

// round 15
// speedup vs baseline: 1.1280x; 1.1280x over previous
#include <cuda_runtime.h>
#include <cstdint>

#define NTOK 8192
#define KT   64
#define CHUNKS (NTOK / KT)   // 128

// passB smem layout (float indices) — R8 map
#define GOFF   0                 // g_s[128][8]
#define UOFF   1024              // u_s[2][64*72]
#define UBUF   4608
#define EOFF   10240             // e_s[2][128*68]
#define EBUF   8704
#define STOFF  1024              // st_s[128][74] epilogue alias
#define SMEM_FLOATS 27648        // 110592 bytes

// Scratch (allocation-free rule: __device__ globals)
__device__ float d_F [2 * NTOK * 8];
__device__ float d_GT[2 * NTOK * 8];
__device__ float d_VT[2 * NTOK * 64];
__device__ float d_invden[2 * NTOK];

__device__ __forceinline__ uint32_t to_tf32(float x) {
    uint32_t r; asm("cvt.rna.tf32.f32 %0, %1;" : "=r"(r) : "f"(x)); return r;
}
__device__ __forceinline__ void mma_tf32(float* d, uint32_t a0, uint32_t a1,
                                         uint32_t a2, uint32_t a3,
                                         uint32_t b0, uint32_t b1) {
    asm volatile(
        "mma.sync.aligned.m16n8k8.row.col.f32.tf32.tf32.f32 "
        "{%0,%1,%2,%3}, {%4,%5,%6,%7}, {%8,%9}, {%0,%1,%2,%3};"
        : "+f"(d[0]), "+f"(d[1]), "+f"(d[2]), "+f"(d[3])
        : "r"(a0), "r"(a1), "r"(a2), "r"(a3), "r"(b0), "r"(b1));
}
__device__ __forceinline__ void ldsm_x4(uint32_t& r0, uint32_t& r1,
                                        uint32_t& r2, uint32_t& r3, uint32_t addr) {
    asm volatile("ldmatrix.sync.aligned.m8n8.x4.shared.b16 {%0,%1,%2,%3}, [%4];"
                 : "=r"(r0), "=r"(r1), "=r"(r2), "=r"(r3) : "r"(addr));
}
__device__ __forceinline__ uint32_t smem_u32(const void* p) {
    uint32_t a;
    asm("{ .reg .u64 t; cvta.to.shared.u64 t, %1; cvt.u32.u64 %0, t; }" : "=r"(a) : "l"(p));
    return a;
}

// ---------------------------------------------------------------------------
// Kernel 1 (proven, 26us): projections.  grid (128,2) x 256.
// ---------------------------------------------------------------------------
__global__ __launch_bounds__(256) void proj_kernel(
    const float* __restrict__ x1, const float* __restrict__ x2,
    const float* __restrict__ Wf, const float* __restrict__ bf,
    const float* __restrict__ Wg, const float* __restrict__ bg,
    const float* __restrict__ Wh1, const float* __restrict__ bh1,
    const float* __restrict__ Wh2, const float* __restrict__ bh2)
{
    const int input = blockIdx.y;
    const float* __restrict__ x  = input ? x2  : x1;
    const float* __restrict__ Wh = input ? Wh2 : Wh1;
    const float* __restrict__ bh = input ? bh2 : bh1;

    __shared__ float x_s[64][65];
    __shared__ float Wh_s[64 * 64];
    __shared__ float Wfg_s[16 * 64];
    __shared__ float bh_s[64], bfg_s[16];

    const int tid = threadIdx.x;
    for (int i = tid; i < 64 * 64; i += 256) Wh_s[i] = Wh[i];
    for (int i = tid; i < 16 * 64; i += 256) Wfg_s[i] = (i < 512) ? Wf[i] : Wg[i - 512];
    if (tid < 64) bh_s[tid] = bh[tid];
    if (tid < 16) bfg_s[tid] = (tid < 8) ? bf[tid] : bg[tid - 8];

    const int n0 = blockIdx.x * 64;
    for (int i = tid; i < 64 * 64; i += 256) {
        const int c = i >> 6, t = i & 63;
        x_s[c][t] = x[(size_t)c * NTOK + n0 + t];
    }
    __syncthreads();

    const int tok = tid & 63, og = tid >> 6;
    const int n = n0 + tok;

    float xr[64];
    #pragma unroll
    for (int c = 0; c < 64; c++) xr[c] = x_s[c][tok];

    float* VT = d_VT + (size_t)(input * NTOK + n) * 64 + og * 16;
    #pragma unroll
    for (int grp = 0; grp < 4; grp++) {
        float vo[4];
        #pragma unroll
        for (int u = 0; u < 4; u++) {
            const int o = og * 16 + grp * 4 + u;
            float a = bh_s[o];
            const float4* w4 = (const float4*)&Wh_s[o * 64];
            #pragma unroll
            for (int q = 0; q < 16; q++) {
                float4 w = w4[q];
                a = fmaf(w.x, xr[4*q+0], a); a = fmaf(w.y, xr[4*q+1], a);
                a = fmaf(w.z, xr[4*q+2], a); a = fmaf(w.w, xr[4*q+3], a);
            }
            vo[u] = a;
        }
        *(float4*)&VT[grp * 4] = make_float4(vo[0], vo[1], vo[2], vo[3]);
    }

    if (og < 2) {
        float fo[8];
        #pragma unroll
        for (int o8 = 0; o8 < 8; o8++) {
            const int o = og * 8 + o8;
            float a = bfg_s[o];
            const float4* w4 = (const float4*)&Wfg_s[o * 64];
            #pragma unroll
            for (int q = 0; q < 16; q++) {
                float4 w = w4[q];
                a = fmaf(w.x, xr[4*q+0], a); a = fmaf(w.y, xr[4*q+1], a);
                a = fmaf(w.z, xr[4*q+2], a); a = fmaf(w.w, xr[4*q+3], a);
            }
            fo[o8] = a;
        }
        float4* dst = (og == 0) ? (float4*)&d_F [(size_t)(input * NTOK + n) * 8]
                                : (float4*)&d_GT[(size_t)(input * NTOK + n) * 8];
        dst[0] = make_float4(fo[0], fo[1], fo[2], fo[3]);
        dst[1] = make_float4(fo[4], fo[5], fo[6], fo[7]);
    }
}

// ---------------------------------------------------------------------------
// Kernel 2 (R13, proven): invden via tf32 MMA logits.  grid (64,2) x 256.
// All warps walk the same m-window in lockstep (L1 locality is the win).
// ---------------------------------------------------------------------------
__global__ __launch_bounds__(256) void passA_kernel()
{
    const int input = blockIdx.y;
    const int tid = threadIdx.x;
    const int wid = tid >> 5, lane = tid & 31;
    const int g4 = lane >> 2, q4 = lane & 3;
    const int nr = blockIdx.x * 128 + wid * 16;

    const float* F = d_F + (size_t)(input * NTOK + nr) * 8;
    const uint32_t a0 = to_tf32(F[ g4      * 8 + q4]);
    const uint32_t a1 = to_tf32(F[(g4 + 8) * 8 + q4]);
    const uint32_t a2 = to_tf32(F[ g4      * 8 + q4 + 4]);
    const uint32_t a3 = to_tf32(F[(g4 + 8) * 8 + q4 + 4]);

    const float* G = d_GT + (size_t)input * NTOK * 8;
    float sum0 = 0.f, sum1 = 0.f;

    for (int m0 = 0; m0 < NTOK; m0 += 64) {
        #pragma unroll
        for (int t = 0; t < 8; t++) {
            const float* gp = G + (size_t)(m0 + t * 8 + g4) * 8;
            const uint32_t b0 = to_tf32(__ldg(gp + q4));
            const uint32_t b1 = to_tf32(__ldg(gp + q4 + 4));
            float d[4] = {0.f, 0.f, 0.f, 0.f};
            mma_tf32(d, a0, a1, a2, a3, b0, b1);
            sum0 += __expf(d[0]) + __expf(d[1]);
            sum1 += __expf(d[2]) + __expf(d[3]);
        }
    }
    sum0 += __shfl_xor_sync(0xffffffffu, sum0, 1);
    sum0 += __shfl_xor_sync(0xffffffffu, sum0, 2);
    sum1 += __shfl_xor_sync(0xffffffffu, sum1, 1);
    sum1 += __shfl_xor_sync(0xffffffffu, sum1, 2);
    if (q4 == 0) {
        d_invden[input * NTOK + nr + g4]     = 1.0f / sum0;
        d_invden[input * NTOK + nr + g4 + 8] = 1.0f / sum1;
    }
}

// ---------------------------------------------------------------------------
// Kernel 3 (R13, proven 303us): passB.  Warp tiles 32m x 32c, 2-way k-split.
// grid (64,2) x 512.
// ---------------------------------------------------------------------------
__global__ __launch_bounds__(512, 1) void passB_kernel(
    const float* __restrict__ x1, const float* __restrict__ x2,
    const float* __restrict__ g1, const float* __restrict__ g2,
    float* __restrict__ out)
{
    extern __shared__ float smf[];
    float*    g_s  = smf + GOFF;
    uint32_t* u_s  = (uint32_t*)(smf + UOFF);
    uint32_t* e_s  = (uint32_t*)(smf + EOFF);
    float*    st_s = smf + STOFF;

    const int tid = threadIdx.x;
    const int wid = tid >> 5, lane = tid & 31;
    const int g4 = lane >> 2, q4 = lane & 3;
    const int input = blockIdx.y;
    const int m_base = blockIdx.x * 128;

    {
        const float* src = d_GT + (size_t)input * NTOK * 8 + (size_t)m_base * 8;
        for (int i = tid; i < 128 * 8; i += 512) g_s[i] = src[i];
    }

    const int n_e = tid & 63, mgrp = tid >> 6;
    const float* VT  = d_VT + (size_t)input * NTOK * 64;
    const float* INV = d_invden + input * NTOK;
    const float4* Fb = (const float4*)(d_F + (size_t)input * NTOK * 8);

    const int mrow  = (wid & 3) * 32;
    const int chalf = (wid >> 2) & 1;
    const int khalf = wid >> 3;
    const int cb    = chalf * 4;

    const uint32_t e_smaddr = smem_u32(e_s);
    const uint32_t a_row = (uint32_t)(mrow + (lane & 7) + (((lane >> 3) & 1) << 3));
    const uint32_t a_base_off = (a_row * 68u + (((lane >> 4) & 1) << 2)) * 4u;

    float acc[2][4][4];
    #pragma unroll
    for (int mt = 0; mt < 2; mt++)
        #pragma unroll
        for (int t = 0; t < 4; t++)
            #pragma unroll
            for (int r = 0; r < 4; r++) acc[mt][t][r] = 0.f;

    float4 fA, fB, vv[2]; float iv[2];

#define LOADG(ch_)                                                             \
    {                                                                          \
        const int nn = (ch_) * KT;                                             \
        fA = Fb[(size_t)(nn + n_e) * 2]; fB = Fb[(size_t)(nn + n_e) * 2 + 1];  \
        _Pragma("unroll")                                                      \
        for (int k = 0; k < 2; k++) {                                          \
            const int idx = tid + 512 * k;                                     \
            const int n = idx >> 4, c4 = idx & 15;                             \
            vv[k] = ((const float4*)VT)[(size_t)(nn + n) * 16 + c4];           \
            iv[k] = INV[nn + n];                                               \
        }                                                                      \
    }

#define GENSTORE(bufi)                                                         \
    {                                                                          \
        uint32_t* ub = u_s + (bufi) * UBUF;                                    \
        uint32_t* eb = e_s + (bufi) * EBUF;                                    \
        _Pragma("unroll")                                                      \
        for (int k = 0; k < 2; k++) {                                          \
            const int idx = tid + 512 * k;                                     \
            const int n = idx >> 4, c4 = idx & 15;                             \
            uint4 p;                                                           \
            p.x = to_tf32(vv[k].x * iv[k]); p.y = to_tf32(vv[k].y * iv[k]);    \
            p.z = to_tf32(vv[k].z * iv[k]); p.w = to_tf32(vv[k].w * iv[k]);    \
            *(uint4*)&ub[n * 72 + c4 * 4] = p;                                 \
        }                                                                      \
        _Pragma("unroll")                                                      \
        for (int j = 0; j < 16; j++) {                                         \
            const int m = mgrp * 16 + j;                                       \
            const float4 ga = *(const float4*)&g_s[m * 8];                     \
            const float4 gb = *(const float4*)&g_s[m * 8 + 4];                 \
            float s = fA.x * ga.x;                                             \
            s = fmaf(fA.y, ga.y, s); s = fmaf(fA.z, ga.z, s);                  \
            s = fmaf(fA.w, ga.w, s);                                           \
            s = fmaf(fB.x, gb.x, s); s = fmaf(fB.y, gb.y, s);                  \
            s = fmaf(fB.z, gb.z, s); s = fmaf(fB.w, gb.w, s);                  \
            eb[m * 68 + n_e] = to_tf32(__expf(s));                             \
        }                                                                      \
    }

    LOADG(0);
    GENSTORE(0);
    LOADG(1);
    __syncthreads();

    for (int chunk = 0; chunk < CHUNKS; chunk++) {
        const int buf = chunk & 1;

        if (chunk + 1 < CHUNKS) {
            GENSTORE(buf ^ 1);
            if (chunk + 2 < CHUNKS) LOADG(chunk + 2);
        }

        {
            const uint32_t* ub = u_s + buf * UBUF;
            const uint32_t abase = e_smaddr + (uint32_t)(buf * EBUF * 4) + a_base_off;
            #pragma unroll
            for (int kl = 0; kl < 4; kl++) {
                const int kk = khalf * 4 + kl;
                uint32_t a0, a1, a2, a3, c0r, c1r, c2r, c3r;
                ldsm_x4(a0, a1, a2, a3, abase + (uint32_t)kk * 32u);
                ldsm_x4(c0r, c1r, c2r, c3r, abase + 4352u + (uint32_t)kk * 32u);
                #pragma unroll
                for (int ct = 0; ct < 4; ct++) {
                    const uint32_t b0 = ub[(kk * 8 + q4)     * 72 + (cb + ct) * 8 + g4];
                    const uint32_t b1 = ub[(kk * 8 + q4 + 4) * 72 + (cb + ct) * 8 + g4];
                    mma_tf32(acc[0][ct], a0, a1, a2, a3, b0, b1);
                    mma_tf32(acc[1][ct], c0r, c1r, c2r, c3r, b0, b1);
                }
            }
        }
        __syncthreads();
    }
#undef LOADG
#undef GENSTORE

    // ---- k-reduction through st_s, then epilogue ----
    if (khalf == 1) {
        #pragma unroll
        for (int mt = 0; mt < 2; mt++)
            #pragma unroll
            for (int ct = 0; ct < 4; ct++) {
                const int c = (cb + ct) * 8 + q4 * 2;
                const int r0 = mrow + mt * 16 + g4;
                *(float2*)&st_s[ r0      * 74 + c] = make_float2(acc[mt][ct][0], acc[mt][ct][1]);
                *(float2*)&st_s[(r0 + 8) * 74 + c] = make_float2(acc[mt][ct][2], acc[mt][ct][3]);
            }
    }
    __syncthreads();
    if (khalf == 0) {
        #pragma unroll
        for (int mt = 0; mt < 2; mt++)
            #pragma unroll
            for (int ct = 0; ct < 4; ct++) {
                const int c = (cb + ct) * 8 + q4 * 2;
                const int r0 = mrow + mt * 16 + g4;
                float2 p0 = *(float2*)&st_s[ r0      * 74 + c];
                float2 p1 = *(float2*)&st_s[(r0 + 8) * 74 + c];
                p0.x += acc[mt][ct][0]; p0.y += acc[mt][ct][1];
                p1.x += acc[mt][ct][2]; p1.y += acc[mt][ct][3];
                *(float2*)&st_s[ r0      * 74 + c] = p0;
                *(float2*)&st_s[(r0 + 8) * 74 + c] = p1;
            }
    }
    __syncthreads();
    {
        const float* __restrict__ x = input ? x2 : x1;
        const float gamma = input ? __ldg(g2) : __ldg(g1);
        #pragma unroll
        for (int j = 0; j < 4; j++) {
            const int c = wid * 4 + j;
            const size_t rowx = (size_t)c * NTOK + m_base;
            const size_t rowo = (size_t)(input * 64 + c) * NTOK + m_base;
            #pragma unroll
            for (int jj = 0; jj < 4; jj++) {
                const int m = lane + 32 * jj;
                out[rowo + m] = fmaf(gamma, st_s[m * 74 + c], x[rowx + m]);
            }
        }
    }
}

// ---------------------------------------------------------------------------
extern "C" void kernel_launch(void* const* d_in, const int* in_sizes, int n_in,
                              void* d_out, int out_size)
{
    (void)in_sizes; (void)n_in; (void)out_size;
    const float* x1  = (const float*)d_in[0];
    const float* x2  = (const float*)d_in[1];
    const float* Wf  = (const float*)d_in[2];
    const float* bf  = (const float*)d_in[3];
    const float* Wg  = (const float*)d_in[4];
    const float* bg  = (const float*)d_in[5];
    const float* Wh1 = (const float*)d_in[6];
    const float* bh1 = (const float*)d_in[7];
    const float* Wh2 = (const float*)d_in[8];
    const float* bh2 = (const float*)d_in[9];
    const float* g1  = (const float*)d_in[10];
    const float* g2  = (const float*)d_in[11];
    float* out = (float*)d_out;

    cudaFuncSetAttribute(passB_kernel, cudaFuncAttributeMaxDynamicSharedMemorySize,
                         SMEM_FLOATS * 4);

    dim3 gp(NTOK / 64, 2);
    proj_kernel<<<gp, 256>>>(x1, x2, Wf, bf, Wg, bg, Wh1, bh1, Wh2, bh2);
    dim3 ga(NTOK / 64, 2);
    passA_kernel<<<ga, 256>>>();
    dim3 gb(NTOK / 128, 2);
    passB_kernel<<<gb, 512, SMEM_FLOATS * 4>>>(x1, x2, g1, g2, out);
}

// round 16
// speedup vs baseline: 1.2965x; 1.1494x over previous
#include <cuda_runtime.h>
#include <cstdint>

#define NTOK 8192
#define KT   64
#define CHUNKS (NTOK / KT)   // 128

// passB smem: g_s[128][8] | 4 stages of (u[64][72], e[128][68])
#define SOFF(s)  (1024 + (s) * 13312)
#define STOFF    1024                  // st_s[128][74] epilogue alias (stage 0)
#define SMEM_FLOATS 54272              // 217088 bytes

// Scratch (allocation-free rule: __device__ globals)
__device__ float d_F [2 * NTOK * 8];
__device__ float d_GT[2 * NTOK * 8];
__device__ float d_VT[2 * NTOK * 64];
__device__ float d_invden[2 * NTOK];

__device__ __forceinline__ uint32_t to_tf32(float x) {
    uint32_t r; asm("cvt.rna.tf32.f32 %0, %1;" : "=r"(r) : "f"(x)); return r;
}
__device__ __forceinline__ void mma_tf32(float* d, uint32_t a0, uint32_t a1,
                                         uint32_t a2, uint32_t a3,
                                         uint32_t b0, uint32_t b1) {
    asm volatile(
        "mma.sync.aligned.m16n8k8.row.col.f32.tf32.tf32.f32 "
        "{%0,%1,%2,%3}, {%4,%5,%6,%7}, {%8,%9}, {%0,%1,%2,%3};"
        : "+f"(d[0]), "+f"(d[1]), "+f"(d[2]), "+f"(d[3])
        : "r"(a0), "r"(a1), "r"(a2), "r"(a3), "r"(b0), "r"(b1));
}
__device__ __forceinline__ void ldsm_x4(uint32_t& r0, uint32_t& r1,
                                        uint32_t& r2, uint32_t& r3, uint32_t addr) {
    asm volatile("ldmatrix.sync.aligned.m8n8.x4.shared.b16 {%0,%1,%2,%3}, [%4];"
                 : "=r"(r0), "=r"(r1), "=r"(r2), "=r"(r3) : "r"(addr));
}
__device__ __forceinline__ uint32_t smem_u32(const void* p) {
    uint32_t a;
    asm("{ .reg .u64 t; cvta.to.shared.u64 t, %1; cvt.u32.u64 %0, t; }" : "=r"(a) : "l"(p));
    return a;
}

// ---------------------------------------------------------------------------
// Kernel 1 (proven, 26us): projections.  grid (128,2) x 256.
// ---------------------------------------------------------------------------
__global__ __launch_bounds__(256) void proj_kernel(
    const float* __restrict__ x1, const float* __restrict__ x2,
    const float* __restrict__ Wf, const float* __restrict__ bf,
    const float* __restrict__ Wg, const float* __restrict__ bg,
    const float* __restrict__ Wh1, const float* __restrict__ bh1,
    const float* __restrict__ Wh2, const float* __restrict__ bh2)
{
    const int input = blockIdx.y;
    const float* __restrict__ x  = input ? x2  : x1;
    const float* __restrict__ Wh = input ? Wh2 : Wh1;
    const float* __restrict__ bh = input ? bh2 : bh1;

    __shared__ float x_s[64][65];
    __shared__ float Wh_s[64 * 64];
    __shared__ float Wfg_s[16 * 64];
    __shared__ float bh_s[64], bfg_s[16];

    const int tid = threadIdx.x;
    for (int i = tid; i < 64 * 64; i += 256) Wh_s[i] = Wh[i];
    for (int i = tid; i < 16 * 64; i += 256) Wfg_s[i] = (i < 512) ? Wf[i] : Wg[i - 512];
    if (tid < 64) bh_s[tid] = bh[tid];
    if (tid < 16) bfg_s[tid] = (tid < 8) ? bf[tid] : bg[tid - 8];

    const int n0 = blockIdx.x * 64;
    for (int i = tid; i < 64 * 64; i += 256) {
        const int c = i >> 6, t = i & 63;
        x_s[c][t] = x[(size_t)c * NTOK + n0 + t];
    }
    __syncthreads();

    const int tok = tid & 63, og = tid >> 6;
    const int n = n0 + tok;

    float xr[64];
    #pragma unroll
    for (int c = 0; c < 64; c++) xr[c] = x_s[c][tok];

    float* VT = d_VT + (size_t)(input * NTOK + n) * 64 + og * 16;
    #pragma unroll
    for (int grp = 0; grp < 4; grp++) {
        float vo[4];
        #pragma unroll
        for (int u = 0; u < 4; u++) {
            const int o = og * 16 + grp * 4 + u;
            float a = bh_s[o];
            const float4* w4 = (const float4*)&Wh_s[o * 64];
            #pragma unroll
            for (int q = 0; q < 16; q++) {
                float4 w = w4[q];
                a = fmaf(w.x, xr[4*q+0], a); a = fmaf(w.y, xr[4*q+1], a);
                a = fmaf(w.z, xr[4*q+2], a); a = fmaf(w.w, xr[4*q+3], a);
            }
            vo[u] = a;
        }
        *(float4*)&VT[grp * 4] = make_float4(vo[0], vo[1], vo[2], vo[3]);
    }

    if (og < 2) {
        float fo[8];
        #pragma unroll
        for (int o8 = 0; o8 < 8; o8++) {
            const int o = og * 8 + o8;
            float a = bfg_s[o];
            const float4* w4 = (const float4*)&Wfg_s[o * 64];
            #pragma unroll
            for (int q = 0; q < 16; q++) {
                float4 w = w4[q];
                a = fmaf(w.x, xr[4*q+0], a); a = fmaf(w.y, xr[4*q+1], a);
                a = fmaf(w.z, xr[4*q+2], a); a = fmaf(w.w, xr[4*q+3], a);
            }
            fo[o8] = a;
        }
        float4* dst = (og == 0) ? (float4*)&d_F [(size_t)(input * NTOK + n) * 8]
                                : (float4*)&d_GT[(size_t)(input * NTOK + n) * 8];
        dst[0] = make_float4(fo[0], fo[1], fo[2], fo[3]);
        dst[1] = make_float4(fo[4], fo[5], fo[6], fo[7]);
    }
}

// ---------------------------------------------------------------------------
// Kernel 2: invden.  grid (128,2) x 256 — 64 rows per block, warp-pairs share
// 16 rows splitting the 8 sub-tile loop 2-way (2 CTAs/SM, lockstep m-windows).
// ---------------------------------------------------------------------------
__global__ __launch_bounds__(256) void passA_kernel()
{
    const int input = blockIdx.y;
    const int tid = threadIdx.x;
    const int wid = tid >> 5, lane = tid & 31;
    const int g4 = lane >> 2, q4 = lane & 3;
    const int wpair = wid >> 1, thalf = wid & 1;
    const int nr = blockIdx.x * 64 + wpair * 16;

    __shared__ float part[8][16];

    const float* F = d_F + (size_t)(input * NTOK + nr) * 8;
    const uint32_t a0 = to_tf32(F[ g4      * 8 + q4]);
    const uint32_t a1 = to_tf32(F[(g4 + 8) * 8 + q4]);
    const uint32_t a2 = to_tf32(F[ g4      * 8 + q4 + 4]);
    const uint32_t a3 = to_tf32(F[(g4 + 8) * 8 + q4 + 4]);

    const float* G = d_GT + (size_t)input * NTOK * 8;
    float sum0 = 0.f, sum1 = 0.f;

    for (int m0 = 0; m0 < NTOK; m0 += 64) {
        #pragma unroll
        for (int th = 0; th < 4; th++) {
            const int t = thalf * 4 + th;
            const float* gp = G + (size_t)(m0 + t * 8 + g4) * 8;
            const uint32_t b0 = to_tf32(__ldg(gp + q4));
            const uint32_t b1 = to_tf32(__ldg(gp + q4 + 4));
            float d[4] = {0.f, 0.f, 0.f, 0.f};
            mma_tf32(d, a0, a1, a2, a3, b0, b1);
            sum0 += __expf(d[0]) + __expf(d[1]);
            sum1 += __expf(d[2]) + __expf(d[3]);
        }
    }
    sum0 += __shfl_xor_sync(0xffffffffu, sum0, 1);
    sum0 += __shfl_xor_sync(0xffffffffu, sum0, 2);
    sum1 += __shfl_xor_sync(0xffffffffu, sum1, 1);
    sum1 += __shfl_xor_sync(0xffffffffu, sum1, 2);
    if (q4 == 0) {
        part[wid][g4]     = sum0;
        part[wid][g4 + 8] = sum1;
    }
    __syncthreads();
    if (thalf == 0 && q4 == 0) {
        d_invden[input * NTOK + nr + g4] =
            1.0f / (part[wid][g4] + part[wid + 1][g4]);
        d_invden[input * NTOK + nr + g4 + 8] =
            1.0f / (part[wid][g4 + 8] + part[wid + 1][g4 + 8]);
    }
}

// ---------------------------------------------------------------------------
// Kernel 3: passB — R13 inner code, 4-stage ring, one barrier per 2 chunks.
// grid (64,2) x 512.  Warp tiles 32m x 32c, 2-way k-split.
// ---------------------------------------------------------------------------
__global__ __launch_bounds__(512, 1) void passB_kernel(
    const float* __restrict__ x1, const float* __restrict__ x2,
    const float* __restrict__ g1, const float* __restrict__ g2,
    float* __restrict__ out)
{
    extern __shared__ float smf[];
    float* g_s  = smf;                  // [128][8]
    float* st_s = smf + STOFF;

    const int tid = threadIdx.x;
    const int wid = tid >> 5, lane = tid & 31;
    const int g4 = lane >> 2, q4 = lane & 3;
    const int input = blockIdx.y;
    const int m_base = blockIdx.x * 128;

    {
        const float* src = d_GT + (size_t)input * NTOK * 8 + (size_t)m_base * 8;
        for (int i = tid; i < 128 * 8; i += 512) g_s[i] = src[i];
    }

    const int n_e = tid & 63, mgrp = tid >> 6;
    const float* VT  = d_VT + (size_t)input * NTOK * 64;
    const float* INV = d_invden + input * NTOK;
    const float4* Fb = (const float4*)(d_F + (size_t)input * NTOK * 8);

    const int mrow  = (wid & 3) * 32;
    const int chalf = (wid >> 2) & 1;
    const int khalf = wid >> 3;
    const int cb    = chalf * 4;

    const uint32_t smbase = smem_u32(smf);
    const uint32_t a_row = (uint32_t)(mrow + (lane & 7) + (((lane >> 3) & 1) << 3));
    const uint32_t a_base_off = (a_row * 68u + (((lane >> 4) & 1) << 2)) * 4u;

    float acc[2][4][4];
    #pragma unroll
    for (int mt = 0; mt < 2; mt++)
        #pragma unroll
        for (int t = 0; t < 4; t++)
            #pragma unroll
            for (int r = 0; r < 4; r++) acc[mt][t][r] = 0.f;

    float4 fA, fB, vv[2]; float iv[2];

#define LOADG(ch_)                                                             \
    {                                                                          \
        const int nn = (ch_) * KT;                                             \
        fA = Fb[(size_t)(nn + n_e) * 2]; fB = Fb[(size_t)(nn + n_e) * 2 + 1];  \
        _Pragma("unroll")                                                      \
        for (int k = 0; k < 2; k++) {                                          \
            const int idx = tid + 512 * k;                                     \
            const int n = idx >> 4, c4 = idx & 15;                             \
            vv[k] = ((const float4*)VT)[(size_t)(nn + n) * 16 + c4];           \
            iv[k] = INV[nn + n];                                               \
        }                                                                      \
    }

#define GENSTORE(bufi)                                                         \
    {                                                                          \
        uint32_t* ub = (uint32_t*)(smf + SOFF(bufi));                          \
        uint32_t* eb = ub + 4608;                                              \
        _Pragma("unroll")                                                      \
        for (int k = 0; k < 2; k++) {                                          \
            const int idx = tid + 512 * k;                                     \
            const int n = idx >> 4, c4 = idx & 15;                             \
            uint4 p;                                                           \
            p.x = to_tf32(vv[k].x * iv[k]); p.y = to_tf32(vv[k].y * iv[k]);    \
            p.z = to_tf32(vv[k].z * iv[k]); p.w = to_tf32(vv[k].w * iv[k]);    \
            *(uint4*)&ub[n * 72 + c4 * 4] = p;                                 \
        }                                                                      \
        _Pragma("unroll")                                                      \
        for (int j = 0; j < 16; j++) {                                         \
            const int m = mgrp * 16 + j;                                       \
            const float4 ga = *(const float4*)&g_s[m * 8];                     \
            const float4 gb = *(const float4*)&g_s[m * 8 + 4];                 \
            float s = fA.x * ga.x;                                             \
            s = fmaf(fA.y, ga.y, s); s = fmaf(fA.z, ga.z, s);                  \
            s = fmaf(fA.w, ga.w, s);                                           \
            s = fmaf(fB.x, gb.x, s); s = fmaf(fB.y, gb.y, s);                  \
            s = fmaf(fB.z, gb.z, s); s = fmaf(fB.w, gb.w, s);                  \
            eb[m * 68 + n_e] = to_tf32(__expf(s));                             \
        }                                                                      \
    }

#define MMAPH(bufi)                                                            \
    {                                                                          \
        const uint32_t* ub = (const uint32_t*)(smf + SOFF(bufi));              \
        const uint32_t abase = smbase + (uint32_t)((SOFF(bufi) + 4608) * 4)    \
                               + a_base_off;                                   \
        _Pragma("unroll")                                                      \
        for (int kl = 0; kl < 4; kl++) {                                       \
            const int kk = khalf * 4 + kl;                                     \
            uint32_t a0, a1, a2, a3, c0r, c1r, c2r, c3r;                       \
            ldsm_x4(a0, a1, a2, a3, abase + (uint32_t)kk * 32u);               \
            ldsm_x4(c0r, c1r, c2r, c3r, abase + 4352u + (uint32_t)kk * 32u);   \
            _Pragma("unroll")                                                  \
            for (int ct = 0; ct < 4; ct++) {                                   \
                const uint32_t b0 = ub[(kk * 8 + q4)     * 72 + (cb + ct) * 8 + g4]; \
                const uint32_t b1 = ub[(kk * 8 + q4 + 4) * 72 + (cb + ct) * 8 + g4]; \
                mma_tf32(acc[0][ct], a0, a1, a2, a3, b0, b1);                  \
                mma_tf32(acc[1][ct], c0r, c1r, c2r, c3r, b0, b1);              \
            }                                                                  \
        }                                                                      \
    }

    LOADG(0);
    GENSTORE(0);
    LOADG(1);
    GENSTORE(1);
    LOADG(2);
    __syncthreads();

    for (int c = 0; c < CHUNKS; c += 2) {
        if (c + 2 < CHUNKS) GENSTORE((c + 2) & 3);
        if (c + 3 < CHUNKS) LOADG(c + 3);
        MMAPH(c & 3);
        if (c + 3 < CHUNKS) GENSTORE((c + 3) & 3);
        MMAPH((c + 1) & 3);
        if (c + 4 < CHUNKS) LOADG(c + 4);
        __syncthreads();
    }
#undef LOADG
#undef GENSTORE
#undef MMAPH

    // ---- k-reduction through st_s, then epilogue ----
    if (khalf == 1) {
        #pragma unroll
        for (int mt = 0; mt < 2; mt++)
            #pragma unroll
            for (int ct = 0; ct < 4; ct++) {
                const int c = (cb + ct) * 8 + q4 * 2;
                const int r0 = mrow + mt * 16 + g4;
                *(float2*)&st_s[ r0      * 74 + c] = make_float2(acc[mt][ct][0], acc[mt][ct][1]);
                *(float2*)&st_s[(r0 + 8) * 74 + c] = make_float2(acc[mt][ct][2], acc[mt][ct][3]);
            }
    }
    __syncthreads();
    if (khalf == 0) {
        #pragma unroll
        for (int mt = 0; mt < 2; mt++)
            #pragma unroll
            for (int ct = 0; ct < 4; ct++) {
                const int c = (cb + ct) * 8 + q4 * 2;
                const int r0 = mrow + mt * 16 + g4;
                float2 p0 = *(float2*)&st_s[ r0      * 74 + c];
                float2 p1 = *(float2*)&st_s[(r0 + 8) * 74 + c];
                p0.x += acc[mt][ct][0]; p0.y += acc[mt][ct][1];
                p1.x += acc[mt][ct][2]; p1.y += acc[mt][ct][3];
                *(float2*)&st_s[ r0      * 74 + c] = p0;
                *(float2*)&st_s[(r0 + 8) * 74 + c] = p1;
            }
    }
    __syncthreads();
    {
        const float* __restrict__ x = input ? x2 : x1;
        const float gamma = input ? __ldg(g2) : __ldg(g1);
        #pragma unroll
        for (int j = 0; j < 4; j++) {
            const int c = wid * 4 + j;
            const size_t rowx = (size_t)c * NTOK + m_base;
            const size_t rowo = (size_t)(input * 64 + c) * NTOK + m_base;
            #pragma unroll
            for (int jj = 0; jj < 4; jj++) {
                const int m = lane + 32 * jj;
                out[rowo + m] = fmaf(gamma, st_s[m * 74 + c], x[rowx + m]);
            }
        }
    }
}

// ---------------------------------------------------------------------------
extern "C" void kernel_launch(void* const* d_in, const int* in_sizes, int n_in,
                              void* d_out, int out_size)
{
    (void)in_sizes; (void)n_in; (void)out_size;
    const float* x1  = (const float*)d_in[0];
    const float* x2  = (const float*)d_in[1];
    const float* Wf  = (const float*)d_in[2];
    const float* bf  = (const float*)d_in[3];
    const float* Wg  = (const float*)d_in[4];
    const float* bg  = (const float*)d_in[5];
    const float* Wh1 = (const float*)d_in[6];
    const float* bh1 = (const float*)d_in[7];
    const float* Wh2 = (const float*)d_in[8];
    const float* bh2 = (const float*)d_in[9];
    const float* g1  = (const float*)d_in[10];
    const float* g2  = (const float*)d_in[11];
    float* out = (float*)d_out;

    cudaFuncSetAttribute(passB_kernel, cudaFuncAttributeMaxDynamicSharedMemorySize,
                         SMEM_FLOATS * 4);

    dim3 gp(NTOK / 64, 2);
    proj_kernel<<<gp, 256>>>(x1, x2, Wf, bf, Wg, bg, Wh1, bh1, Wh2, bh2);
    dim3 ga(NTOK / 64, 2);
    passA_kernel<<<ga, 256>>>();
    dim3 gb(NTOK / 128, 2);
    passB_kernel<<<gb, 512, SMEM_FLOATS * 4>>>(x1, x2, g1, g2, out);
}

// round 17
// speedup vs baseline: 1.3573x; 1.0469x over previous
#include <cuda_runtime.h>
#include <cstdint>

#define NTOK 8192
#define KT   64
#define CHUNKS (NTOK / KT)   // 128

// passB smem: g_s[128][8] | 4 stages of (u[64][72], e[128][68])
#define SOFF(s)  (1024 + (s) * 13312)
#define STOFF    1024                  // st_s[128][74] epilogue alias (stage 0)
#define SMEM_FLOATS 54272              // 217088 bytes

// Scratch (allocation-free rule: __device__ globals)
__device__ float d_F [2 * NTOK * 8];
__device__ float d_GT[2 * NTOK * 8];
__device__ float d_VT[2 * NTOK * 64];
__device__ float d_invden[2 * NTOK];

__device__ __forceinline__ uint32_t to_tf32(float x) {
    uint32_t r; asm("cvt.rna.tf32.f32 %0, %1;" : "=r"(r) : "f"(x)); return r;
}
__device__ __forceinline__ void mma_tf32(float* d, uint32_t a0, uint32_t a1,
                                         uint32_t a2, uint32_t a3,
                                         uint32_t b0, uint32_t b1) {
    asm volatile(
        "mma.sync.aligned.m16n8k8.row.col.f32.tf32.tf32.f32 "
        "{%0,%1,%2,%3}, {%4,%5,%6,%7}, {%8,%9}, {%0,%1,%2,%3};"
        : "+f"(d[0]), "+f"(d[1]), "+f"(d[2]), "+f"(d[3])
        : "r"(a0), "r"(a1), "r"(a2), "r"(a3), "r"(b0), "r"(b1));
}
__device__ __forceinline__ void ldsm_x4(uint32_t& r0, uint32_t& r1,
                                        uint32_t& r2, uint32_t& r3, uint32_t addr) {
    asm volatile("ldmatrix.sync.aligned.m8n8.x4.shared.b16 {%0,%1,%2,%3}, [%4];"
                 : "=r"(r0), "=r"(r1), "=r"(r2), "=r"(r3) : "r"(addr));
}
__device__ __forceinline__ uint32_t smem_u32(const void* p) {
    uint32_t a;
    asm("{ .reg .u64 t; cvta.to.shared.u64 t, %1; cvt.u32.u64 %0, t; }" : "=r"(a) : "l"(p));
    return a;
}

// ---------------------------------------------------------------------------
// Kernel 1: projections.  grid (128,2) x 256, now 2 CTAs/SM.
// ---------------------------------------------------------------------------
__global__ __launch_bounds__(256, 2) void proj_kernel(
    const float* __restrict__ x1, const float* __restrict__ x2,
    const float* __restrict__ Wf, const float* __restrict__ bf,
    const float* __restrict__ Wg, const float* __restrict__ bg,
    const float* __restrict__ Wh1, const float* __restrict__ bh1,
    const float* __restrict__ Wh2, const float* __restrict__ bh2)
{
    const int input = blockIdx.y;
    const float* __restrict__ x  = input ? x2  : x1;
    const float* __restrict__ Wh = input ? Wh2 : Wh1;
    const float* __restrict__ bh = input ? bh2 : bh1;

    __shared__ float x_s[64][65];
    __shared__ float Wh_s[64 * 64];
    __shared__ float Wfg_s[16 * 64];
    __shared__ float bh_s[64], bfg_s[16];

    const int tid = threadIdx.x;
    for (int i = tid; i < 64 * 64; i += 256) Wh_s[i] = Wh[i];
    for (int i = tid; i < 16 * 64; i += 256) Wfg_s[i] = (i < 512) ? Wf[i] : Wg[i - 512];
    if (tid < 64) bh_s[tid] = bh[tid];
    if (tid < 16) bfg_s[tid] = (tid < 8) ? bf[tid] : bg[tid - 8];

    const int n0 = blockIdx.x * 64;
    for (int i = tid; i < 64 * 64; i += 256) {
        const int c = i >> 6, t = i & 63;
        x_s[c][t] = x[(size_t)c * NTOK + n0 + t];
    }
    __syncthreads();

    const int tok = tid & 63, og = tid >> 6;
    const int n = n0 + tok;

    float xr[64];
    #pragma unroll
    for (int c = 0; c < 64; c++) xr[c] = x_s[c][tok];

    float* VT = d_VT + (size_t)(input * NTOK + n) * 64 + og * 16;
    #pragma unroll
    for (int grp = 0; grp < 4; grp++) {
        float vo[4];
        #pragma unroll
        for (int u = 0; u < 4; u++) {
            const int o = og * 16 + grp * 4 + u;
            float a = bh_s[o];
            const float4* w4 = (const float4*)&Wh_s[o * 64];
            #pragma unroll
            for (int q = 0; q < 16; q++) {
                float4 w = w4[q];
                a = fmaf(w.x, xr[4*q+0], a); a = fmaf(w.y, xr[4*q+1], a);
                a = fmaf(w.z, xr[4*q+2], a); a = fmaf(w.w, xr[4*q+3], a);
            }
            vo[u] = a;
        }
        *(float4*)&VT[grp * 4] = make_float4(vo[0], vo[1], vo[2], vo[3]);
    }

    if (og < 2) {
        float fo[8];
        #pragma unroll
        for (int o8 = 0; o8 < 8; o8++) {
            const int o = og * 8 + o8;
            float a = bfg_s[o];
            const float4* w4 = (const float4*)&Wfg_s[o * 64];
            #pragma unroll
            for (int q = 0; q < 16; q++) {
                float4 w = w4[q];
                a = fmaf(w.x, xr[4*q+0], a); a = fmaf(w.y, xr[4*q+1], a);
                a = fmaf(w.z, xr[4*q+2], a); a = fmaf(w.w, xr[4*q+3], a);
            }
            fo[o8] = a;
        }
        float4* dst = (og == 0) ? (float4*)&d_F [(size_t)(input * NTOK + n) * 8]
                                : (float4*)&d_GT[(size_t)(input * NTOK + n) * 8];
        dst[0] = make_float4(fo[0], fo[1], fo[2], fo[3]);
        dst[1] = make_float4(fo[4], fo[5], fo[6], fo[7]);
    }
}

// ---------------------------------------------------------------------------
// Kernel 2: invden.  grid (128,2) x 512 — 64 rows per block; warp-QUAD shares
// 16 rows splitting the 8 sub-tile loop 4-way. Lockstep m-windows (L1 reuse).
// ---------------------------------------------------------------------------
__global__ __launch_bounds__(512) void passA_kernel()
{
    const int input = blockIdx.y;
    const int tid = threadIdx.x;
    const int wid = tid >> 5, lane = tid & 31;
    const int g4 = lane >> 2, q4 = lane & 3;
    const int wquad = wid >> 2, tq = wid & 3;
    const int nr = blockIdx.x * 64 + wquad * 16;

    __shared__ float part[16][16];

    const float* F = d_F + (size_t)(input * NTOK + nr) * 8;
    const uint32_t a0 = to_tf32(F[ g4      * 8 + q4]);
    const uint32_t a1 = to_tf32(F[(g4 + 8) * 8 + q4]);
    const uint32_t a2 = to_tf32(F[ g4      * 8 + q4 + 4]);
    const uint32_t a3 = to_tf32(F[(g4 + 8) * 8 + q4 + 4]);

    const float* G = d_GT + (size_t)input * NTOK * 8;
    float sum0 = 0.f, sum1 = 0.f;

    for (int m0 = 0; m0 < NTOK; m0 += 64) {
        #pragma unroll
        for (int th = 0; th < 2; th++) {
            const int t = tq * 2 + th;
            const float* gp = G + (size_t)(m0 + t * 8 + g4) * 8;
            const uint32_t b0 = to_tf32(__ldg(gp + q4));
            const uint32_t b1 = to_tf32(__ldg(gp + q4 + 4));
            float d[4] = {0.f, 0.f, 0.f, 0.f};
            mma_tf32(d, a0, a1, a2, a3, b0, b1);
            sum0 += __expf(d[0]) + __expf(d[1]);
            sum1 += __expf(d[2]) + __expf(d[3]);
        }
    }
    sum0 += __shfl_xor_sync(0xffffffffu, sum0, 1);
    sum0 += __shfl_xor_sync(0xffffffffu, sum0, 2);
    sum1 += __shfl_xor_sync(0xffffffffu, sum1, 1);
    sum1 += __shfl_xor_sync(0xffffffffu, sum1, 2);
    if (q4 == 0) {
        part[wid][g4]     = sum0;
        part[wid][g4 + 8] = sum1;
    }
    __syncthreads();
    if (tq == 0 && q4 == 0) {
        const int w = wid;
        d_invden[input * NTOK + nr + g4] =
            1.0f / (part[w][g4] + part[w + 1][g4] + part[w + 2][g4] + part[w + 3][g4]);
        d_invden[input * NTOK + nr + g4 + 8] =
            1.0f / (part[w][g4 + 8] + part[w + 1][g4 + 8] +
                    part[w + 2][g4 + 8] + part[w + 3][g4 + 8]);
    }
}

// ---------------------------------------------------------------------------
// Kernel 3 (R16, proven ~285us): passB — 4-stage ring, barrier per 2 chunks.
// grid (64,2) x 512.  Warp tiles 32m x 32c, 2-way k-split.
// ---------------------------------------------------------------------------
__global__ __launch_bounds__(512, 1) void passB_kernel(
    const float* __restrict__ x1, const float* __restrict__ x2,
    const float* __restrict__ g1, const float* __restrict__ g2,
    float* __restrict__ out)
{
    extern __shared__ float smf[];
    float* g_s  = smf;                  // [128][8]
    float* st_s = smf + STOFF;

    const int tid = threadIdx.x;
    const int wid = tid >> 5, lane = tid & 31;
    const int g4 = lane >> 2, q4 = lane & 3;
    const int input = blockIdx.y;
    const int m_base = blockIdx.x * 128;

    {
        const float* src = d_GT + (size_t)input * NTOK * 8 + (size_t)m_base * 8;
        for (int i = tid; i < 128 * 8; i += 512) g_s[i] = src[i];
    }

    const int n_e = tid & 63, mgrp = tid >> 6;
    const float* VT  = d_VT + (size_t)input * NTOK * 64;
    const float* INV = d_invden + input * NTOK;
    const float4* Fb = (const float4*)(d_F + (size_t)input * NTOK * 8);

    const int mrow  = (wid & 3) * 32;
    const int chalf = (wid >> 2) & 1;
    const int khalf = wid >> 3;
    const int cb    = chalf * 4;

    const uint32_t smbase = smem_u32(smf);
    const uint32_t a_row = (uint32_t)(mrow + (lane & 7) + (((lane >> 3) & 1) << 3));
    const uint32_t a_base_off = (a_row * 68u + (((lane >> 4) & 1) << 2)) * 4u;

    float acc[2][4][4];
    #pragma unroll
    for (int mt = 0; mt < 2; mt++)
        #pragma unroll
        for (int t = 0; t < 4; t++)
            #pragma unroll
            for (int r = 0; r < 4; r++) acc[mt][t][r] = 0.f;

    float4 fA, fB, vv[2]; float iv[2];

#define LOADG(ch_)                                                             \
    {                                                                          \
        const int nn = (ch_) * KT;                                             \
        fA = Fb[(size_t)(nn + n_e) * 2]; fB = Fb[(size_t)(nn + n_e) * 2 + 1];  \
        _Pragma("unroll")                                                      \
        for (int k = 0; k < 2; k++) {                                          \
            const int idx = tid + 512 * k;                                     \
            const int n = idx >> 4, c4 = idx & 15;                             \
            vv[k] = ((const float4*)VT)[(size_t)(nn + n) * 16 + c4];           \
            iv[k] = INV[nn + n];                                               \
        }                                                                      \
    }

#define GENSTORE(bufi)                                                         \
    {                                                                          \
        uint32_t* ub = (uint32_t*)(smf + SOFF(bufi));                          \
        uint32_t* eb = ub + 4608;                                              \
        _Pragma("unroll")                                                      \
        for (int k = 0; k < 2; k++) {                                          \
            const int idx = tid + 512 * k;                                     \
            const int n = idx >> 4, c4 = idx & 15;                             \
            uint4 p;                                                           \
            p.x = to_tf32(vv[k].x * iv[k]); p.y = to_tf32(vv[k].y * iv[k]);    \
            p.z = to_tf32(vv[k].z * iv[k]); p.w = to_tf32(vv[k].w * iv[k]);    \
            *(uint4*)&ub[n * 72 + c4 * 4] = p;                                 \
        }                                                                      \
        _Pragma("unroll")                                                      \
        for (int j = 0; j < 16; j++) {                                         \
            const int m = mgrp * 16 + j;                                       \
            const float4 ga = *(const float4*)&g_s[m * 8];                     \
            const float4 gb = *(const float4*)&g_s[m * 8 + 4];                 \
            float s = fA.x * ga.x;                                             \
            s = fmaf(fA.y, ga.y, s); s = fmaf(fA.z, ga.z, s);                  \
            s = fmaf(fA.w, ga.w, s);                                           \
            s = fmaf(fB.x, gb.x, s); s = fmaf(fB.y, gb.y, s);                  \
            s = fmaf(fB.z, gb.z, s); s = fmaf(fB.w, gb.w, s);                  \
            eb[m * 68 + n_e] = to_tf32(__expf(s));                             \
        }                                                                      \
    }

#define MMAPH(bufi)                                                            \
    {                                                                          \
        const uint32_t* ub = (const uint32_t*)(smf + SOFF(bufi));              \
        const uint32_t abase = smbase + (uint32_t)((SOFF(bufi) + 4608) * 4)    \
                               + a_base_off;                                   \
        _Pragma("unroll")                                                      \
        for (int kl = 0; kl < 4; kl++) {                                       \
            const int kk = khalf * 4 + kl;                                     \
            uint32_t a0, a1, a2, a3, c0r, c1r, c2r, c3r;                       \
            ldsm_x4(a0, a1, a2, a3, abase + (uint32_t)kk * 32u);               \
            ldsm_x4(c0r, c1r, c2r, c3r, abase + 4352u + (uint32_t)kk * 32u);   \
            _Pragma("unroll")                                                  \
            for (int ct = 0; ct < 4; ct++) {                                   \
                const uint32_t b0 = ub[(kk * 8 + q4)     * 72 + (cb + ct) * 8 + g4]; \
                const uint32_t b1 = ub[(kk * 8 + q4 + 4) * 72 + (cb + ct) * 8 + g4]; \
                mma_tf32(acc[0][ct], a0, a1, a2, a3, b0, b1);                  \
                mma_tf32(acc[1][ct], c0r, c1r, c2r, c3r, b0, b1);              \
            }                                                                  \
        }                                                                      \
    }

    LOADG(0);
    GENSTORE(0);
    LOADG(1);
    GENSTORE(1);
    LOADG(2);
    __syncthreads();

    for (int c = 0; c < CHUNKS; c += 2) {
        if (c + 2 < CHUNKS) GENSTORE((c + 2) & 3);
        if (c + 3 < CHUNKS) LOADG(c + 3);
        MMAPH(c & 3);
        if (c + 3 < CHUNKS) GENSTORE((c + 3) & 3);
        MMAPH((c + 1) & 3);
        if (c + 4 < CHUNKS) LOADG(c + 4);
        __syncthreads();
    }
#undef LOADG
#undef GENSTORE
#undef MMAPH

    // ---- k-reduction through st_s, then epilogue ----
    if (khalf == 1) {
        #pragma unroll
        for (int mt = 0; mt < 2; mt++)
            #pragma unroll
            for (int ct = 0; ct < 4; ct++) {
                const int c = (cb + ct) * 8 + q4 * 2;
                const int r0 = mrow + mt * 16 + g4;
                *(float2*)&st_s[ r0      * 74 + c] = make_float2(acc[mt][ct][0], acc[mt][ct][1]);
                *(float2*)&st_s[(r0 + 8) * 74 + c] = make_float2(acc[mt][ct][2], acc[mt][ct][3]);
            }
    }
    __syncthreads();
    if (khalf == 0) {
        #pragma unroll
        for (int mt = 0; mt < 2; mt++)
            #pragma unroll
            for (int ct = 0; ct < 4; ct++) {
                const int c = (cb + ct) * 8 + q4 * 2;
                const int r0 = mrow + mt * 16 + g4;
                float2 p0 = *(float2*)&st_s[ r0      * 74 + c];
                float2 p1 = *(float2*)&st_s[(r0 + 8) * 74 + c];
                p0.x += acc[mt][ct][0]; p0.y += acc[mt][ct][1];
                p1.x += acc[mt][ct][2]; p1.y += acc[mt][ct][3];
                *(float2*)&st_s[ r0      * 74 + c] = p0;
                *(float2*)&st_s[(r0 + 8) * 74 + c] = p1;
            }
    }
    __syncthreads();
    {
        const float* __restrict__ x = input ? x2 : x1;
        const float gamma = input ? __ldg(g2) : __ldg(g1);
        #pragma unroll
        for (int j = 0; j < 4; j++) {
            const int c = wid * 4 + j;
            const size_t rowx = (size_t)c * NTOK + m_base;
            const size_t rowo = (size_t)(input * 64 + c) * NTOK + m_base;
            #pragma unroll
            for (int jj = 0; jj < 4; jj++) {
                const int m = lane + 32 * jj;
                out[rowo + m] = fmaf(gamma, st_s[m * 74 + c], x[rowx + m]);
            }
        }
    }
}

// ---------------------------------------------------------------------------
extern "C" void kernel_launch(void* const* d_in, const int* in_sizes, int n_in,
                              void* d_out, int out_size)
{
    (void)in_sizes; (void)n_in; (void)out_size;
    const float* x1  = (const float*)d_in[0];
    const float* x2  = (const float*)d_in[1];
    const float* Wf  = (const float*)d_in[2];
    const float* bf  = (const float*)d_in[3];
    const float* Wg  = (const float*)d_in[4];
    const float* bg  = (const float*)d_in[5];
    const float* Wh1 = (const float*)d_in[6];
    const float* bh1 = (const float*)d_in[7];
    const float* Wh2 = (const float*)d_in[8];
    const float* bh2 = (const float*)d_in[9];
    const float* g1  = (const float*)d_in[10];
    const float* g2  = (const float*)d_in[11];
    float* out = (float*)d_out;

    cudaFuncSetAttribute(passB_kernel, cudaFuncAttributeMaxDynamicSharedMemorySize,
                         SMEM_FLOATS * 4);

    dim3 gp(NTOK / 64, 2);
    proj_kernel<<<gp, 256>>>(x1, x2, Wf, bf, Wg, bg, Wh1, bh1, Wh2, bh2);
    dim3 ga(NTOK / 64, 2);
    passA_kernel<<<ga, 512>>>();
    dim3 gb(NTOK / 128, 2);
    passB_kernel<<<gb, 512, SMEM_FLOATS * 4>>>(x1, x2, g1, g2, out);
}